// round 13
// baseline (speedup 1.0000x reference)
#include <cuda_runtime.h>
#include <cstdint>

// Input order (metadata):
// 0 exposure_params [200] f32 | 1 vignetting_params [4,3,5] f32
// 2 color_params [200,8] f32  | 3 crf_params [4,3,4] f32
// 4 rgb_in [H,W,3] f32        | 5 pixel_coords [H,W,2] f32 (unused; reconstructed)
// 6 resolution_w i32 | 7 resolution_h i32 | 8 camera_idx i32 | 9 frame_idx i32

// Shared param block layout:
//  0..2  PX[3] (=-2cx)   3..5 PY[3] (=-2cy)   6..8 PC[3] (=cx^2+cy^2)
//  9..11 A1[3] (=a1*inv) 12..14 A2[3] (=a2*inv^2) 15..17 A3[3] (=a3*inv^3)
// 18..26 M[9] exposure-folded color matrix (row-major)
// 27..29 G[3] gamma
// 30..32 KA[3] (=1+C0) 33..35 KB[3] (=C1-C0) 36..38 KC[3] (=-C1)
//        [y + y(1-y)(C0+C1 y) == y*(KA + y*(KB + y*KC)), C0=q1+q3, C1=q2-q3]
// 39     crf_on

__device__ __forceinline__ float mufu_lg2(float x) {
    float r; asm("lg2.approx.f32 %0, %1;" : "=f"(r) : "f"(x)); return r;
}
__device__ __forceinline__ float mufu_ex2(float x) {
    float r; asm("ex2.approx.f32 %0, %1;" : "=f"(r) : "f"(x)); return r;
}

__global__ void __launch_bounds__(256) ppisp_fused(
    const float* __restrict__ exposure,
    const float* __restrict__ vig,
    const float* __restrict__ color,
    const float* __restrict__ crf,
    const float* __restrict__ in,
    float* __restrict__ out,
    const int* __restrict__ rw,
    const int* __restrict__ rh,
    const int* __restrict__ cam,
    const int* __restrict__ frm,
    unsigned npix) {
    __shared__ __align__(16) float sp[40];
    __shared__ unsigned sW, sShift, sMask, sPow2;

    // ---- warp-parallel fold: lanes 0..13 own disjoint slices (proven in R11/R12;
    // keeps per-lane register footprint ~12, no serial thread-0 array code). ----
    if (threadIdx.x < 32) {
        const int lane = threadIdx.x;
        const int f = frm[0];
        const int c = cam[0];
        const unsigned Wu = (unsigned)rw[0];
        const float Wf = (float)Wu;
        const float Hf = (float)rh[0];

        if (lane < 3) {
            const int ch = lane;
            float PX = 0.f, PY = 0.f, PC = 0.f, A1 = 0.f, A2 = 0.f, A3 = 0.f;
            float G = 1.f, KA = 1.f, KB = 0.f, KC = 0.f;
            if (c >= 0) {
                const float norm2 = (0.5f * Wf) * (0.5f * Wf) + (0.5f * Hf) * (0.5f * Hf);
                const float inv = 1.0f / norm2;
                const float* vp = vig + ((size_t)c * 3 + ch) * 5;
                const float cx = (0.5f + vp[0]) * Wf;
                const float cy = (0.5f + vp[1]) * Hf;
                PX = -2.0f * cx;
                PY = -2.0f * cy;
                PC = fmaf(cx, cx, cy * cy);
                A1 = vp[2] * inv;
                A2 = vp[3] * inv * inv;
                A3 = vp[4] * inv * inv * inv;
                const float* q = crf + ((size_t)c * 3 + ch) * 4;
                G  = expf(q[0]);
                const float C0 = q[1] + q[3];
                const float C1 = q[2] - q[3];
                KA = 1.0f + C0;
                KB = C1 - C0;
                KC = -C1;
            }
            sp[0 + ch]  = PX;
            sp[3 + ch]  = PY;
            sp[6 + ch]  = PC;
            sp[9 + ch]  = A1;
            sp[12 + ch] = A2;
            sp[15 + ch] = A3;
            sp[27 + ch] = G;
            sp[30 + ch] = KA;
            sp[33 + ch] = KB;
            sp[36 + ch] = KC;
        } else if (lane >= 4 && lane < 13) {
            const int i = lane - 4;            // 0..8, row-major
            float Mi;
            if (f >= 0) {
                if (i == 8) {
                    Mi = 1.0f;
                } else {
                    Mi = color[(size_t)f * 8 + i];
                    if (i == 0 || i == 4) Mi += 1.0f;
                }
                Mi *= expf(exposure[f]);
            } else {
                Mi = (i == 0 || i == 4 || i == 8) ? 1.0f : 0.0f;
            }
            sp[18 + i] = Mi;
        } else if (lane == 13) {
            sW = (unsigned)rw[0];
            const unsigned Wx = (unsigned)rw[0];
            const bool pow2 = (Wx != 0u) && ((Wx & (Wx - 1u)) == 0u);
            sPow2 = pow2 ? 1u : 0u;
            sMask = Wx - 1u;
            unsigned s = 0;
            if (pow2) { unsigned w = Wx; while (w > 1u) { w >>= 1; s++; } }
            sShift = s;
            sp[39] = (c >= 0) ? 1.0f : 0.0f;
        }
    }
    __syncthreads();

    const unsigned gid = blockIdx.x * blockDim.x + threadIdx.x;
    const unsigned p0 = gid * 4u;
    if (p0 >= npix) return;

    const unsigned W = sW;
    unsigned row, col;
    if (sPow2) {                   // uniform branch; W=4096 -> shift/mask, no IDIV
        row = p0 >> sShift;
        col = p0 & sMask;
    } else {
        row = p0 / W;
        col = p0 - row * W;
    }

    if (p0 + 3u < npix && col + 3u < W) {
        // ---- fast path: 4 pixels, one row; STAGE-MAJOR so every smem param is
        // loaded exactly ONCE per thread and reused across the 4 pixels. ----
        const float4* in4 = reinterpret_cast<const float4*>(in);
        float4* out4 = reinterpret_cast<float4*>(out);
        const size_t base = (size_t)gid * 3u;
        float4 A = in4[base + 0];
        float4 B = in4[base + 1];
        float4 C = in4[base + 2];

        float vr[4], vg[4], vb[4];
        vr[0] = A.x; vg[0] = A.y; vb[0] = A.z;
        vr[1] = A.w; vg[1] = B.x; vb[1] = B.y;
        vr[2] = B.z; vg[2] = B.w; vb[2] = C.x;
        vr[3] = C.y; vg[3] = C.z; vb[3] = C.w;

        const float y = (float)row + 0.5f;
        const float x0 = (float)col + 0.5f;
        float xs[4];
#pragma unroll
        for (int p = 0; p < 4; p++) xs[p] = x0 + (float)p;

        // --- stage 1: vignetting (exposure folded into M), channel-major ---
        {
            const float PX = sp[0], PY = sp[3], PC = sp[6];
            const float a1 = sp[9], a2 = sp[12], a3 = sp[15];
            const float ty = fmaf(y, y + PY, PC);
#pragma unroll
            for (int p = 0; p < 4; p++) {
                const float r2 = fmaf(xs[p], xs[p] + PX, ty);
                float h = fmaf(r2, a3, a2);
                h = fmaf(r2, h, a1);
                vr[p] = fmaf(vr[p], r2 * h, vr[p]);
            }
        }
        {
            const float PX = sp[1], PY = sp[4], PC = sp[7];
            const float a1 = sp[10], a2 = sp[13], a3 = sp[16];
            const float ty = fmaf(y, y + PY, PC);
#pragma unroll
            for (int p = 0; p < 4; p++) {
                const float r2 = fmaf(xs[p], xs[p] + PX, ty);
                float h = fmaf(r2, a3, a2);
                h = fmaf(r2, h, a1);
                vg[p] = fmaf(vg[p], r2 * h, vg[p]);
            }
        }
        {
            const float PX = sp[2], PY = sp[5], PC = sp[8];
            const float a1 = sp[11], a2 = sp[14], a3 = sp[17];
            const float ty = fmaf(y, y + PY, PC);
#pragma unroll
            for (int p = 0; p < 4; p++) {
                const float r2 = fmaf(xs[p], xs[p] + PX, ty);
                float h = fmaf(r2, a3, a2);
                h = fmaf(r2, h, a1);
                vb[p] = fmaf(vb[p], r2 * h, vb[p]);
            }
        }

        // --- stage 2: 3x3 color matrix (exposure folded in) ---
        {
            const float m0 = sp[18], m1 = sp[19], m2 = sp[20];
            const float m3 = sp[21], m4 = sp[22], m5 = sp[23];
            const float m6 = sp[24], m7 = sp[25], m8 = sp[26];
#pragma unroll
            for (int p = 0; p < 4; p++) {
                const float r = vr[p], g = vg[p], b = vb[p];
                vr[p] = fmaf(m0, r, fmaf(m1, g, m2 * b));
                vg[p] = fmaf(m3, r, fmaf(m4, g, m5 * b));
                vb[p] = fmaf(m6, r, fmaf(m7, g, m8 * b));
            }
        }

        // --- stage 3: CRF gamma + refolded cubic, channel-major ---
        if (sp[39] > 0.5f) {
            {
                const float G = sp[27], KA = sp[30], KB = sp[33], KC = sp[36];
#pragma unroll
                for (int p = 0; p < 4; p++) {
                    const float xc = __saturatef(vr[p]);
                    const float yv = mufu_ex2(G * mufu_lg2(xc)); // xc=0 -> 0, correct
                    vr[p] = yv * fmaf(yv, fmaf(yv, KC, KB), KA);
                }
            }
            {
                const float G = sp[28], KA = sp[31], KB = sp[34], KC = sp[37];
#pragma unroll
                for (int p = 0; p < 4; p++) {
                    const float xc = __saturatef(vg[p]);
                    const float yv = mufu_ex2(G * mufu_lg2(xc));
                    vg[p] = yv * fmaf(yv, fmaf(yv, KC, KB), KA);
                }
            }
            {
                const float G = sp[29], KA = sp[32], KB = sp[35], KC = sp[38];
#pragma unroll
                for (int p = 0; p < 4; p++) {
                    const float xc = __saturatef(vb[p]);
                    const float yv = mufu_ex2(G * mufu_lg2(xc));
                    vb[p] = yv * fmaf(yv, fmaf(yv, KC, KB), KA);
                }
            }
        }

        A.x = vr[0]; A.y = vg[0]; A.z = vb[0];
        A.w = vr[1]; B.x = vg[1]; B.y = vb[1];
        B.z = vr[2]; B.w = vg[2]; C.x = vb[2];
        C.y = vr[3]; C.z = vg[3]; C.w = vb[3];

        __stcs(&out4[base + 0], A);
        __stcs(&out4[base + 1], B);
        __stcs(&out4[base + 2], C);
    } else {
        // ---- generic tail / row-wrap path (cold; per-use smem reads OK) ----
        unsigned rr = row, cc = col;
        const unsigned pend = (p0 + 4u < npix) ? (p0 + 4u) : npix;
        const bool crf_on = (sp[39] > 0.5f);
        for (unsigned p = p0; p < pend; p++) {
            float v3[3];
            v3[0] = in[(size_t)p * 3 + 0];
            v3[1] = in[(size_t)p * 3 + 1];
            v3[2] = in[(size_t)p * 3 + 2];
            const float yy = (float)rr + 0.5f;
            const float xx = (float)cc + 0.5f;
#pragma unroll
            for (int ch = 0; ch < 3; ch++) {
                const float ty = fmaf(yy, yy + sp[3 + ch], sp[6 + ch]);
                const float r2 = fmaf(xx, xx + sp[0 + ch], ty);
                float h = fmaf(r2, sp[15 + ch], sp[12 + ch]);
                h = fmaf(r2, h, sp[9 + ch]);
                v3[ch] = fmaf(v3[ch], r2 * h, v3[ch]);
            }
            float o3[3];
#pragma unroll
            for (int i = 0; i < 3; i++)
                o3[i] = fmaf(sp[18 + i * 3], v3[0],
                         fmaf(sp[19 + i * 3], v3[1], sp[20 + i * 3] * v3[2]));
            if (crf_on) {
#pragma unroll
                for (int ch = 0; ch < 3; ch++) {
                    const float xc = __saturatef(o3[ch]);
                    const float yv = mufu_ex2(sp[27 + ch] * mufu_lg2(xc));
                    o3[ch] = yv * fmaf(yv, fmaf(yv, sp[36 + ch], sp[33 + ch]), sp[30 + ch]);
                }
            }
            out[(size_t)p * 3 + 0] = o3[0];
            out[(size_t)p * 3 + 1] = o3[1];
            out[(size_t)p * 3 + 2] = o3[2];
            cc++;
            if (cc == W) { cc = 0u; rr++; }
        }
    }
}

extern "C" void kernel_launch(void* const* d_in, const int* in_sizes, int n_in,
                              void* d_out, int out_size) {
    const float* exposure = (const float*)d_in[0];
    const float* vig      = (const float*)d_in[1];
    const float* color    = (const float*)d_in[2];
    const float* crf      = (const float*)d_in[3];
    const float* rgb_in   = (const float*)d_in[4];
    // d_in[5] = pixel_coords, intentionally unused (reconstructed analytically)
    const int* rw  = (const int*)d_in[6];
    const int* rh  = (const int*)d_in[7];
    const int* cam = (const int*)d_in[8];
    const int* frm = (const int*)d_in[9];
    float* out = (float*)d_out;

    const unsigned npix = (unsigned)(in_sizes[4] / 3);
    const unsigned nthreads = (npix + 3u) / 4u;
    const unsigned blocks = (nthreads + 255u) / 256u;

    // SINGLE graph node (~3.5us per extra node measured): warp-parallel smem
    // fold + stage-major hot loop with one-LDS-per-param access.
    ppisp_fused<<<blocks, 256>>>(exposure, vig, color, crf, rgb_in, out,
                                 rw, rh, cam, frm, npix);
}